// round 5
// baseline (speedup 1.0000x reference)
#include <cuda_runtime.h>
#include <math.h>

#define NC_     80
#define A_TOT   8400
#define B_TOT   32
#define NANCH   (B_TOT * A_TOT)
#define EPS     1e-7f

// global accumulators: 0=tss, 1=cls, 2=iou, 3=dfl
__device__ double g_acc[4];

__global__ void rn_init_kernel() {
    if (threadIdx.x < 4) g_acc[threadIdx.x] = 0.0;
}

__global__ void __launch_bounds__(256) rn_loss_kernel(
    const float* __restrict__ pred_dist,      // (B,A,64)
    const float* __restrict__ pred_scores,    // (B,A,80)
    const float* __restrict__ anchor_points,  // (A,2)
    const float* __restrict__ target_bboxes,  // (B,A,4)
    const float* __restrict__ target_scores)  // (B,A,80)
{
    const int lane = threadIdx.x & 31;
    const int wglob = (blockIdx.x * blockDim.x + threadIdx.x) >> 5;
    const int nwarps = (gridDim.x * blockDim.x) >> 5;

    float cls_acc = 0.f, iou_acc = 0.f, dfl_acc = 0.f, tss_acc = 0.f;

    for (int n = wglob; n < NANCH; n += nwarps) {
        const int aidx = n - (n / A_TOT) * A_TOT;
        const float ax = __ldg(&anchor_points[2 * aidx]);
        const float ay = __ldg(&anchor_points[2 * aidx + 1]);
        const float4 tb = __ldg((const float4*)(target_bboxes) + n);

        // ---------------- focal BCE over 80 classes + tsum ----------------
        const float* xs = pred_scores + (long long)n * NC_;
        const float* ts = target_scores + (long long)n * NC_;
        float tsum = 0.f;
        float clsl = 0.f;
        #pragma unroll
        for (int it = 0; it < 3; it++) {
            int c = lane + it * 32;
            if (c < NC_) {
                float x = __ldg(xs + c);
                float t = __ldg(ts + c);
                tsum += t;
                float axm = fabsf(x);
                float e   = __expf(-axm);
                float l1p = __logf(1.f + e);                 // log1p(exp(-|x|))
                float spx = fmaxf(x, 0.f) + l1p;             // softplus(x)
                float spn = fmaxf(-x, 0.f) + l1p;            // softplus(-x)
                float bce = t * spn + (1.f - t) * spx;
                float inv = __frcp_rn(1.f + e);
                float p   = (x >= 0.f) ? inv : e * inv;      // sigmoid(x)
                float u   = fmaxf(p + t - 2.f * t * p, 0.f); // 1 - p_t
                float af  = 0.75f - 0.5f * t;                // alpha factor
                clsl += bce * af * u * __fsqrt_rn(u);        // * (1-p_t)^1.5
            }
        }
        cls_acc += clsl;
        #pragma unroll
        for (int off = 16; off; off >>= 1)
            tsum += __shfl_xor_sync(0xffffffffu, tsum, off);
        const float w = tsum;                  // bbox_weight (fg already folded in)
        if (lane == 0) tss_acc += tsum;

        // ---------------- DFL softmax / expectation ----------------
        // lane holds bins 2*lane, 2*lane+1; group g = lane>>3 (8 lanes per group)
        const float2 v = __ldg((const float2*)(pred_dist + (long long)n * 64) + lane);
        float m = fmaxf(v.x, v.y);
        #pragma unroll
        for (int off = 4; off; off >>= 1)
            m = fmaxf(m, __shfl_xor_sync(0xffffffffu, m, off));
        const float ex = __expf(v.x - m);
        const float ey = __expf(v.y - m);
        const int b0 = (2 * lane) & 15;
        float se = ex + ey;
        float sb = (float)b0 * ex + (float)(b0 + 1) * ey;
        #pragma unroll
        for (int off = 4; off; off >>= 1) {
            se += __shfl_xor_sync(0xffffffffu, se, off);
            sb += __shfl_xor_sync(0xffffffffu, sb, off);
        }
        const float dist = sb * __frcp_rn(se);               // group expectation
        const float lse  = m + __logf(se);

        // target ltrb for this lane's group
        const int g = lane >> 3;
        float tv;
        if (g == 0)      tv = ax - tb.x;
        else if (g == 1) tv = ay - tb.y;
        else if (g == 2) tv = tb.z - ax;
        else             tv = tb.w - ay;
        tv = fminf(fmaxf(tv, 0.f), 14.99f);
        const float tlf = floorf(tv);
        const int   tl  = (int)tlf;
        const float wl  = tlf + 1.f - tv;
        const float wr  = 1.f - wl;

        // CE contribution: -logp[bin] = lse - logit
        float c0 = (b0 == tl) ? wl : ((b0 == tl + 1) ? wr : 0.f);
        float c1 = (b0 + 1 == tl) ? wl : ((b0 + 1 == tl + 1) ? wr : 0.f);
        dfl_acc += (c0 * (lse - v.x) + c1 * (lse - v.y)) * (0.25f * w);

        // ---------------- CIoU on lane 0 ----------------
        const float d1 = __shfl_sync(0xffffffffu, dist, 8);
        const float d2 = __shfl_sync(0xffffffffu, dist, 16);
        const float d3 = __shfl_sync(0xffffffffu, dist, 24);
        if (lane == 0) {
            const float px1 = ax - dist, py1 = ay - d1;
            const float px2 = ax + d2,   py2 = ay + d3;
            const float w1 = px2 - px1;
            const float h1 = py2 - py1 + EPS;
            const float w2 = tb.z - tb.x;
            const float h2 = tb.w - tb.y + EPS;
            float iw = fminf(px2, tb.z) - fmaxf(px1, tb.x); iw = fmaxf(iw, 0.f);
            float ih = fminf(py2, tb.w) - fmaxf(py1, tb.y); ih = fmaxf(ih, 0.f);
            const float inter = iw * ih;
            const float uni   = w1 * h1 + w2 * h2 - inter + EPS;
            const float iou   = inter / uni;
            const float cw = fmaxf(px2, tb.z) - fminf(px1, tb.x);
            const float ch = fmaxf(py2, tb.w) - fminf(py1, tb.y);
            const float c2 = cw * cw + ch * ch + EPS;
            const float dx = tb.x + tb.z - px1 - px2;
            const float dy = tb.y + tb.w - py1 - py2;
            const float rho2 = (dx * dx + dy * dy) * 0.25f;
            const float dat = atanf(w2 / h2) - atanf(w1 / h1);
            const float vv = (4.0f / (float)(M_PI * M_PI)) * dat * dat;
            const float alpha = vv / (vv - iou + (1.0f + EPS));
            const float ciou = iou - (rho2 / c2 + vv * alpha);
            iou_acc += (1.f - ciou) * w;
        }
    }

    // warp-level final reduction (iou/tss already lane0-only)
    #pragma unroll
    for (int off = 16; off; off >>= 1) {
        cls_acc += __shfl_xor_sync(0xffffffffu, cls_acc, off);
        dfl_acc += __shfl_xor_sync(0xffffffffu, dfl_acc, off);
    }
    if (lane == 0) {
        atomicAdd(&g_acc[0], (double)tss_acc);
        atomicAdd(&g_acc[1], (double)cls_acc);
        atomicAdd(&g_acc[2], (double)iou_acc);
        atomicAdd(&g_acc[3], (double)dfl_acc);
    }
}

__global__ void rn_finalize_kernel(float* __restrict__ out) {
    if (threadIdx.x == 0) {
        double tss = g_acc[0];
        if (tss < 1.0) tss = 1.0;
        out[0] = (float)(7.5 * g_acc[2] / tss);  // box
        out[1] = (float)(0.5 * g_acc[1] / tss);  // cls
        out[2] = (float)(1.5 * g_acc[3] / tss);  // dfl
    }
}

extern "C" void kernel_launch(void* const* d_in, const int* in_sizes, int n_in,
                              void* d_out, int out_size) {
    const float* pred_dist     = (const float*)d_in[0];
    const float* pred_scores   = (const float*)d_in[1];
    const float* anchor_points = (const float*)d_in[2];
    const float* target_bboxes = (const float*)d_in[3];
    const float* target_scores = (const float*)d_in[4];
    // d_in[5] = fg_mask: mathematically redundant (target_scores already masked)

    rn_init_kernel<<<1, 32>>>();
    rn_loss_kernel<<<1184, 256>>>(pred_dist, pred_scores, anchor_points,
                                  target_bboxes, target_scores);
    rn_finalize_kernel<<<1, 32>>>((float*)d_out);
}

// round 7
// speedup vs baseline: 1.5920x; 1.5920x over previous
#include <cuda_runtime.h>
#include <math.h>

#define NC_     80
#define A_TOT   8400
#define NANCH   268800
#define NPAIR   134400
#define EPS     1e-7f
#define TPB     256
#define GRID    1184

// global accumulators: 0=tss, 1=cls, 2=iou, 3=dfl  (+ completion counter)
__device__ double g_acc[4];
__device__ unsigned int g_done;

__global__ void __launch_bounds__(TPB) rn_loss_kernel(
    const float* __restrict__ pred_dist,      // (B,A,64)
    const float* __restrict__ pred_scores,    // (B,A,80)
    const float* __restrict__ anchor_points,  // (A,2)
    const float* __restrict__ target_bboxes,  // (B,A,4)
    const float* __restrict__ target_scores,  // (B,A,80)
    float* __restrict__ out)
{
    const int lane  = threadIdx.x & 31;
    const int l     = lane & 15;      // lane within half-warp
    const int half  = lane >> 4;      // which anchor of the pair
    const int q     = l & 3;          // position within 4-lane side group
    const int g     = l >> 2;         // ltrb side index
    const float b0f = (float)(4 * q); // first DFL bin owned by this lane

    const int wglob  = (blockIdx.x * TPB + threadIdx.x) >> 5;
    const int nwarps = (GRID * TPB) >> 5;

    float cls_acc = 0.f, dfl_acc = 0.f, iou_acc = 0.f, tss_acc = 0.f;

    for (int p = wglob; p < NPAIR; p += nwarps) {
        const int n    = 2 * p + half;
        const int aidx = n - (n / A_TOT) * A_TOT;
        const float2 ap = __ldg((const float2*)anchor_points + aidx);
        const float4 tb = __ldg((const float4*)target_bboxes + n);

        // ---------- focal BCE over 80 classes (16 lanes x 5 iters) ----------
        const float* xs = pred_scores  + (long long)n * NC_;
        const float* ts = target_scores + (long long)n * NC_;
        float tsum = 0.f, clsl = 0.f;
        #pragma unroll
        for (int it = 0; it < 5; it++) {
            const float x = __ldg(xs + l + 16 * it);
            const float t = __ldg(ts + l + 16 * it);
            tsum += t;
            const float e   = __expf(-fabsf(x));
            const float l1p = __logf(1.f + e);                 // log1p(exp(-|x|))
            const float bce = fmaxf(x, 0.f) - x * t + l1p;     // t*sp(-x)+(1-t)*sp(x)
            const float inv = __frcp_rn(1.f + e);
            const float pp  = (x >= 0.f) ? inv : e * inv;      // sigmoid(x)
            const float u   = fmaf(pp, 1.f - 2.f * t, t);      // 1 - p_t  (>=0)
            const float af  = 0.75f - 0.5f * t;                // alpha factor
            clsl = fmaf(bce * af, u * __fsqrt_rn(u), clsl);    // * (1-p_t)^1.5
        }
        cls_acc += clsl;

        // per-anchor tsum: reduce within each 16-lane half
        #pragma unroll
        for (int off = 1; off < 16; off <<= 1)
            tsum += __shfl_xor_sync(0xffffffffu, tsum, off);
        const float w = tsum;                 // bbox_weight (fg already folded in)
        if (l == 0) tss_acc += tsum;

        // ---------- DFL: lane owns 4 bins of one side (float4, coalesced) ----------
        const float4 v = __ldg((const float4*)pred_dist + n * 16 + l);
        const float e0 = __expf(v.x), e1 = __expf(v.y);
        const float e2 = __expf(v.z), e3 = __expf(v.w);
        float se = (e0 + e1) + (e2 + e3);
        float sb = fmaf(b0f, se, fmaf(3.f, e3, fmaf(2.f, e2, e1)));
        // reduce over the 4-lane side group
        se += __shfl_xor_sync(0xffffffffu, se, 1);
        sb += __shfl_xor_sync(0xffffffffu, sb, 1);
        se += __shfl_xor_sync(0xffffffffu, se, 2);
        sb += __shfl_xor_sync(0xffffffffu, sb, 2);
        const float lse  = __logf(se);
        const float dist = sb * __frcp_rn(se);     // softmax @ proj for this side

        // target ltrb for this side
        float tv = (g == 0) ? ap.x - tb.x
                 : (g == 1) ? ap.y - tb.y
                 : (g == 2) ? tb.z - ap.x
                 :            tb.w - ap.y;
        tv = fminf(fmaxf(tv, 0.f), 14.99f);

        // left/right CE weights via tent: c(b) = max(0, 1 - |b - tv|)
        const float c0 = fmaxf(0.f, 1.f - fabsf(b0f       - tv));
        const float c1 = fmaxf(0.f, 1.f - fabsf(b0f + 1.f - tv));
        const float c2 = fmaxf(0.f, 1.f - fabsf(b0f + 2.f - tv));
        const float c3 = fmaxf(0.f, 1.f - fabsf(b0f + 3.f - tv));
        const float csum = (c0 + c1) + (c2 + c3);
        const float cv = fmaf(c0, v.x, fmaf(c1, v.y, fmaf(c2, v.z, c3 * v.w)));
        dfl_acc = fmaf(csum * lse - cv, 0.25f * w, dfl_acc);   // sum -logp * weight

        // ---------- CIoU: gather the 4 side expectations, one lane per anchor ----------
        const int base = lane & 16;
        const float d0 = __shfl_sync(0xffffffffu, dist, base);
        const float d1 = __shfl_sync(0xffffffffu, dist, base + 4);
        const float d2 = __shfl_sync(0xffffffffu, dist, base + 8);
        const float d3 = __shfl_sync(0xffffffffu, dist, base + 12);
        if (l == 0) {   // lanes 0 and 16 run concurrently (both anchors)
            const float px1 = ap.x - d0, py1 = ap.y - d1;
            const float px2 = ap.x + d2, py2 = ap.y + d3;
            const float w1 = px2 - px1, h1 = py2 - py1 + EPS;
            const float w2 = tb.z - tb.x, h2 = tb.w - tb.y + EPS;
            const float iw = fmaxf(fminf(px2, tb.z) - fmaxf(px1, tb.x), 0.f);
            const float ih = fmaxf(fminf(py2, tb.w) - fmaxf(py1, tb.y), 0.f);
            const float inter = iw * ih;
            const float uni = fmaf(w1, h1, fmaf(w2, h2, -inter)) + EPS;
            const float iou = inter * __frcp_rn(uni);
            const float cw = fmaxf(px2, tb.z) - fminf(px1, tb.x);
            const float ch = fmaxf(py2, tb.w) - fminf(py1, tb.y);
            const float c2d = fmaf(cw, cw, ch * ch) + EPS;
            const float dx = tb.x + tb.z - px1 - px2;
            const float dy = tb.y + tb.w - py1 - py2;
            const float rho2 = fmaf(dx, dx, dy * dy) * 0.25f;
            // atan(a)-atan(b) = atan((a-b)/(1+ab))  (a,b > 0)
            const float a = w2 * __frcp_rn(h2);
            const float b = w1 * __frcp_rn(h1);
            const float dat = atanf((a - b) * __frcp_rn(fmaf(a, b, 1.f)));
            const float vv = (4.0f / (float)(M_PI * M_PI)) * dat * dat;
            const float alpha = vv * __frcp_rn(vv - iou + 1.f + EPS);
            const float ciou = iou - fmaf(rho2, __frcp_rn(c2d), vv * alpha);
            iou_acc = fmaf(1.f - ciou, w, iou_acc);
        }
    }

    // ---------- warp reduce ----------
    #pragma unroll
    for (int off = 16; off; off >>= 1) {
        tss_acc += __shfl_xor_sync(0xffffffffu, tss_acc, off);
        cls_acc += __shfl_xor_sync(0xffffffffu, cls_acc, off);
        iou_acc += __shfl_xor_sync(0xffffffffu, iou_acc, off);
        dfl_acc += __shfl_xor_sync(0xffffffffu, dfl_acc, off);
    }

    // ---------- block reduce (smem), then 4 double atomics ----------
    __shared__ float sred[TPB / 32][4];
    const int wid = threadIdx.x >> 5;
    if (lane == 0) {
        sred[wid][0] = tss_acc; sred[wid][1] = cls_acc;
        sred[wid][2] = iou_acc; sred[wid][3] = dfl_acc;
    }
    __syncthreads();
    if (threadIdx.x == 0) {
        float bt = 0.f, bc = 0.f, bi = 0.f, bd = 0.f;
        #pragma unroll
        for (int i = 0; i < TPB / 32; i++) {
            bt += sred[i][0]; bc += sred[i][1];
            bi += sred[i][2]; bd += sred[i][3];
        }
        atomicAdd(&g_acc[0], (double)bt);
        atomicAdd(&g_acc[1], (double)bc);
        atomicAdd(&g_acc[2], (double)bi);
        atomicAdd(&g_acc[3], (double)bd);
        __threadfence();
        const unsigned prev = atomicAdd(&g_done, 1u);
        if (prev == gridDim.x - 1) {   // last block: finalize + reset for replay
            double tss = atomicAdd(&g_acc[0], 0.0);
            const double cls = atomicAdd(&g_acc[1], 0.0);
            const double iou = atomicAdd(&g_acc[2], 0.0);
            const double dfl = atomicAdd(&g_acc[3], 0.0);
            if (tss < 1.0) tss = 1.0;
            out[0] = (float)(7.5 * iou / tss);
            out[1] = (float)(0.5 * cls / tss);
            out[2] = (float)(1.5 * dfl / tss);
            g_acc[0] = 0.0; g_acc[1] = 0.0; g_acc[2] = 0.0; g_acc[3] = 0.0;
            __threadfence();
            g_done = 0u;
        }
    }
}

extern "C" void kernel_launch(void* const* d_in, const int* in_sizes, int n_in,
                              void* d_out, int out_size) {
    const float* pred_dist     = (const float*)d_in[0];
    const float* pred_scores   = (const float*)d_in[1];
    const float* anchor_points = (const float*)d_in[2];
    const float* target_bboxes = (const float*)d_in[3];
    const float* target_scores = (const float*)d_in[4];
    // d_in[5] = fg_mask: redundant (target_scores is already masked by it)

    rn_loss_kernel<<<GRID, TPB>>>(pred_dist, pred_scores, anchor_points,
                                  target_bboxes, target_scores, (float*)d_out);
}

// round 8
// speedup vs baseline: 2.6280x; 1.6508x over previous
#include <cuda_runtime.h>
#include <math.h>

#define NC_     80
#define A_TOT   8400
#define NPAIR   134400
#define EPS     1e-7f
#define TPB     256
#define GRID    888          // 148 SM x 6 blocks: exactly one wave

// global accumulators: 0=tss, 1=cls, 2=iou, 3=dfl  (+ completion counter)
__device__ double g_acc[4];
__device__ unsigned int g_done;

__device__ __forceinline__ float frcp(float x) {
    float r; asm("rcp.approx.f32 %0, %1;" : "=f"(r) : "f"(x)); return r;
}
__device__ __forceinline__ float fsqrt(float x) {
    float r; asm("sqrt.approx.f32 %0, %1;" : "=f"(r) : "f"(x)); return r;
}
// minimax atan, |err| ~1e-7; full range via atan(x) = pi/2 - atan(1/x)
__device__ __forceinline__ float fatan(float x) {
    const float ax = fabsf(x);
    const bool big = ax > 1.f;
    const float z  = big ? frcp(ax) : ax;
    const float z2 = z * z;
    float p = -0.01172120f;
    p = fmaf(p, z2,  0.05265332f);
    p = fmaf(p, z2, -0.11643287f);
    p = fmaf(p, z2,  0.19354346f);
    p = fmaf(p, z2, -0.33262347f);
    p = fmaf(p, z2,  0.99997726f);
    p = p * z;
    float r = big ? (1.57079632679f - p) : p;
    return (x < 0.f) ? -r : r;
}

__global__ void __launch_bounds__(TPB, 6) rn_loss_kernel(
    const float* __restrict__ pred_dist,      // (B,A,64)
    const float* __restrict__ pred_scores,    // (B,A,80)
    const float* __restrict__ anchor_points,  // (A,2)
    const float* __restrict__ target_bboxes,  // (B,A,4)
    const float* __restrict__ target_scores,  // (B,A,80)
    float* __restrict__ out)
{
    const int lane  = threadIdx.x & 31;
    const int l     = lane & 15;      // lane within half-warp
    const int half  = lane >> 4;      // which anchor of the pair
    const int q     = l & 3;          // position within 4-lane side group
    const int g     = l >> 2;         // ltrb side index
    const float b0f = (float)(4 * q); // first DFL bin owned by this lane

    const int wglob  = (blockIdx.x * TPB + threadIdx.x) >> 5;
    const int nwarps = (GRID * TPB) >> 5;

    float cls_acc = 0.f, dfl_acc = 0.f, iou_acc = 0.f, tss_acc = 0.f;

    for (int p = wglob; p < NPAIR; p += nwarps) {
        const int n    = 2 * p + half;
        const int aidx = n - (n / A_TOT) * A_TOT;
        const float2 ap = __ldg((const float2*)anchor_points + aidx);
        const float4 tb = __ldg((const float4*)target_bboxes + n);

        // ---------- focal BCE over 80 classes (16 lanes x 5 iters) ----------
        const float* xs = pred_scores   + (long long)n * NC_;
        const float* ts = target_scores + (long long)n * NC_;
        float tsum = 0.f, clsl = 0.f;
        #pragma unroll
        for (int it = 0; it < 5; it++) {
            const float x = __ldg(xs + l + 16 * it);
            const float t = __ldg(ts + l + 16 * it);
            tsum += t;
            const float e   = __expf(-fabsf(x));
            const float l1p = __logf(1.f + e);                 // log1p(exp(-|x|))
            const float bce = fmaxf(x, 0.f) - x * t + l1p;     // t*sp(-x)+(1-t)*sp(x)
            const float inv = frcp(1.f + e);
            const float pp  = (x >= 0.f) ? inv : e * inv;      // sigmoid(x)
            const float u   = fmaf(pp, 1.f - 2.f * t, t);      // 1 - p_t  (>=0)
            const float af  = 0.75f - 0.5f * t;                // alpha factor
            clsl = fmaf(bce * af, u * fsqrt(u), clsl);         // * (1-p_t)^1.5
        }
        cls_acc += clsl;

        // per-anchor tsum: reduce within each 16-lane half
        #pragma unroll
        for (int off = 1; off < 16; off <<= 1)
            tsum += __shfl_xor_sync(0xffffffffu, tsum, off);
        const float w = tsum;                 // bbox_weight (fg already folded in)
        if (l == 0) tss_acc += tsum;

        // ---------- DFL: lane owns 4 bins of one side (float4, coalesced) ----------
        const float4 v = __ldg((const float4*)pred_dist + n * 16 + l);
        const float e0 = __expf(v.x), e1 = __expf(v.y);
        const float e2 = __expf(v.z), e3 = __expf(v.w);
        float se = (e0 + e1) + (e2 + e3);
        float sb = fmaf(b0f, se, fmaf(3.f, e3, fmaf(2.f, e2, e1)));
        // reduce over the 4-lane side group
        se += __shfl_xor_sync(0xffffffffu, se, 1);
        sb += __shfl_xor_sync(0xffffffffu, sb, 1);
        se += __shfl_xor_sync(0xffffffffu, se, 2);
        sb += __shfl_xor_sync(0xffffffffu, sb, 2);
        const float lse  = __logf(se);
        const float dist = sb * frcp(se);          // softmax @ proj for this side

        // target ltrb for this side
        float tv = (g == 0) ? ap.x - tb.x
                 : (g == 1) ? ap.y - tb.y
                 : (g == 2) ? tb.z - ap.x
                 :            tb.w - ap.y;
        tv = fminf(fmaxf(tv, 0.f), 14.99f);

        // left/right CE weights via tent: c(b) = max(0, 1 - |b - tv|)
        const float c0 = fmaxf(0.f, 1.f - fabsf(b0f       - tv));
        const float c1 = fmaxf(0.f, 1.f - fabsf(b0f + 1.f - tv));
        const float c2 = fmaxf(0.f, 1.f - fabsf(b0f + 2.f - tv));
        const float c3 = fmaxf(0.f, 1.f - fabsf(b0f + 3.f - tv));
        const float csum = (c0 + c1) + (c2 + c3);
        const float cv = fmaf(c0, v.x, fmaf(c1, v.y, fmaf(c2, v.z, c3 * v.w)));
        dfl_acc = fmaf(csum * lse - cv, 0.25f * w, dfl_acc);   // sum -logp * weight

        // ---------- CIoU: gather the 4 side expectations, one lane per anchor ----------
        const int base = lane & 16;
        const float d0 = __shfl_sync(0xffffffffu, dist, base);
        const float d1 = __shfl_sync(0xffffffffu, dist, base + 4);
        const float d2 = __shfl_sync(0xffffffffu, dist, base + 8);
        const float d3 = __shfl_sync(0xffffffffu, dist, base + 12);
        if (l == 0) {   // lanes 0 and 16 run concurrently (both anchors)
            const float px1 = ap.x - d0, py1 = ap.y - d1;
            const float px2 = ap.x + d2, py2 = ap.y + d3;
            const float w1 = px2 - px1, h1 = py2 - py1 + EPS;
            const float w2 = tb.z - tb.x, h2 = tb.w - tb.y + EPS;
            const float iw = fmaxf(fminf(px2, tb.z) - fmaxf(px1, tb.x), 0.f);
            const float ih = fmaxf(fminf(py2, tb.w) - fmaxf(py1, tb.y), 0.f);
            const float inter = iw * ih;
            const float uni = fmaf(w1, h1, fmaf(w2, h2, -inter)) + EPS;
            const float iou = inter * frcp(uni);
            const float cw = fmaxf(px2, tb.z) - fminf(px1, tb.x);
            const float ch = fmaxf(py2, tb.w) - fminf(py1, tb.y);
            const float c2d = fmaf(cw, cw, ch * ch) + EPS;
            const float dx = tb.x + tb.z - px1 - px2;
            const float dy = tb.y + tb.w - py1 - py2;
            const float rho2 = fmaf(dx, dx, dy * dy) * 0.25f;
            // atan(a)-atan(b) = atan((a-b)/(1+ab))  (a,b > 0)
            const float a = w2 * frcp(h2);
            const float b = w1 * frcp(h1);
            const float dat = fatan((a - b) * frcp(fmaf(a, b, 1.f)));
            const float vv = (4.0f / (float)(M_PI * M_PI)) * dat * dat;
            const float alpha = vv * frcp(vv - iou + 1.f + EPS);
            const float ciou = iou - fmaf(rho2, frcp(c2d), vv * alpha);
            iou_acc = fmaf(1.f - ciou, w, iou_acc);
        }
    }

    // ---------- warp reduce ----------
    #pragma unroll
    for (int off = 16; off; off >>= 1) {
        tss_acc += __shfl_xor_sync(0xffffffffu, tss_acc, off);
        cls_acc += __shfl_xor_sync(0xffffffffu, cls_acc, off);
        iou_acc += __shfl_xor_sync(0xffffffffu, iou_acc, off);
        dfl_acc += __shfl_xor_sync(0xffffffffu, dfl_acc, off);
    }

    // ---------- block reduce (smem), then 4 double atomics ----------
    __shared__ float sred[TPB / 32][4];
    const int wid = threadIdx.x >> 5;
    if (lane == 0) {
        sred[wid][0] = tss_acc; sred[wid][1] = cls_acc;
        sred[wid][2] = iou_acc; sred[wid][3] = dfl_acc;
    }
    __syncthreads();
    if (threadIdx.x == 0) {
        float bt = 0.f, bc = 0.f, bi = 0.f, bd = 0.f;
        #pragma unroll
        for (int i = 0; i < TPB / 32; i++) {
            bt += sred[i][0]; bc += sred[i][1];
            bi += sred[i][2]; bd += sred[i][3];
        }
        atomicAdd(&g_acc[0], (double)bt);
        atomicAdd(&g_acc[1], (double)bc);
        atomicAdd(&g_acc[2], (double)bi);
        atomicAdd(&g_acc[3], (double)bd);
        __threadfence();
        const unsigned prev = atomicAdd(&g_done, 1u);
        if (prev == gridDim.x - 1) {   // last block: finalize + reset for replay
            double tss = atomicAdd(&g_acc[0], 0.0);
            const double cls = atomicAdd(&g_acc[1], 0.0);
            const double iou = atomicAdd(&g_acc[2], 0.0);
            const double dfl = atomicAdd(&g_acc[3], 0.0);
            if (tss < 1.0) tss = 1.0;
            out[0] = (float)(7.5 * iou / tss);
            out[1] = (float)(0.5 * cls / tss);
            out[2] = (float)(1.5 * dfl / tss);
            g_acc[0] = 0.0; g_acc[1] = 0.0; g_acc[2] = 0.0; g_acc[3] = 0.0;
            __threadfence();
            g_done = 0u;
        }
    }
}

extern "C" void kernel_launch(void* const* d_in, const int* in_sizes, int n_in,
                              void* d_out, int out_size) {
    const float* pred_dist     = (const float*)d_in[0];
    const float* pred_scores   = (const float*)d_in[1];
    const float* anchor_points = (const float*)d_in[2];
    const float* target_bboxes = (const float*)d_in[3];
    const float* target_scores = (const float*)d_in[4];
    // d_in[5] = fg_mask: redundant (target_scores is already masked by it)

    rn_loss_kernel<<<GRID, TPB>>>(pred_dist, pred_scores, anchor_points,
                                  target_bboxes, target_scores, (float*)d_out);
}